// round 9
// baseline (speedup 1.0000x reference)
#include <cuda_runtime.h>

// Stacked LSTM: B=64, T=512, D=256, H=512, 3 layers. fp32.
// Persistent kernel, 128 blocks x 512 threads, split-phase two-level grid
// barrier per timestep. Block bc owns 4 hidden units => 16 z-columns.
// Per step: 64x16xK GEMM (K = D+H or 2H), K split 16 ways (one warp each,
// 8 k per warp per 128-k chunk), packed f32x2 FFMA.
// Weights resident in smem per layer. A panel staged in 128-k chunks,
// DOUBLE-BUFFERED: one sync per chunk, LDG/STS overlap compute.
// x-region chunks computed between barrier arrive and wait.

#define Bsz 64
#define Tsz 512
#define Dsz 256
#define Hsz 512
#define Gsz 2048
#define NBLK 128
#define NTHR 512

typedef unsigned long long u64;

// dynamic smem (floats):
//   w_s   [1024][16]      16384
//   a_s   [2][64][132]    16896   (two 128-k chunks; row stride 132)
//   zred  [16][64][18]    18432
//   bias  [16]               16
#define SM_WS   0
#define SM_AS   16384
#define SM_ZRED (16384 + 16896)
#define SM_BIAS (16384 + 16896 + 18432)
#define SMEM_FLOATS (16384 + 16896 + 18432 + 16)
#define SMEM_BYTES (SMEM_FLOATS * 4)
#define ABUF 8448   // floats per a_s buffer

__device__ float g_seqA[(size_t)Bsz * Tsz * Hsz];
__device__ float g_seqB[(size_t)Bsz * Tsz * Hsz];
__device__ float g_hbuf[2][Bsz * Hsz];
__device__ unsigned g_cnt[8];
__device__ unsigned g_root = 0;
__device__ unsigned g_gen = 0;

// ---- split-phase two-level grid barrier (snapshot-based; replay-safe) ----
__device__ __forceinline__ void bar_arrive(unsigned* s_my, int grp) {
    __syncthreads();
    if (threadIdx.x == 0) {
        unsigned my;
        asm volatile("ld.relaxed.gpu.u32 %0, [%1];" : "=r"(my) : "l"(&g_gen));
        *s_my = my;
        __threadfence();
        unsigned old = atomicAdd(&g_cnt[grp], 1u);
        if (old == 15u) {
            unsigned rold = atomicAdd(&g_root, 1u);
            if (rold == 7u) {
                #pragma unroll
                for (int i = 0; i < 8; i++) g_cnt[i] = 0;
                g_root = 0;
                __threadfence();
                asm volatile("st.release.gpu.u32 [%0], %1;" :: "l"(&g_gen), "r"(my + 1u));
            }
        }
    }
}
__device__ __forceinline__ void bar_wait(unsigned* s_my) {
    if (threadIdx.x == 0) {
        unsigned my = *s_my, g;
        do {
            asm volatile("ld.acquire.gpu.u32 %0, [%1];" : "=r"(g) : "l"(&g_gen));
        } while (g == my);
    }
    __syncthreads();
}

__device__ __forceinline__ float fsig(float x) {
    return __fdividef(1.0f, 1.0f + __expf(-x));
}
__device__ __forceinline__ float ftanh(float x) {
    float e = __expf(2.0f * x);
    return 1.0f - __fdividef(2.0f, e + 1.0f);
}
__device__ __forceinline__ void fma2(u64& d, u64 a, u64 b) {
    asm("fma.rn.f32x2 %0, %1, %2, %0;" : "+l"(d) : "l"(a), "l"(b));
}
__device__ __forceinline__ u64 rep2(float x) {
    u64 r;
    asm("mov.b64 %0, {%1, %1};" : "=l"(r) : "f"(x));
    return r;
}

extern "C" __global__ void __launch_bounds__(NTHR, 1)
lstm_kernel(const float* __restrict__ x0,
            const float* __restrict__ W0, const float* __restrict__ U0, const float* __restrict__ b0,
            const float* __restrict__ W1, const float* __restrict__ U1, const float* __restrict__ b1,
            const float* __restrict__ W2, const float* __restrict__ U2, const float* __restrict__ b2,
            float* __restrict__ out)
{
    extern __shared__ float smem[];
    float* w_s    = smem + SM_WS;     // [k][16]
    float* a_s    = smem + SM_AS;     // [2][64][132]
    float* zred   = smem + SM_ZRED;   // [16][64][18]
    float* bias_s = smem + SM_BIAS;   // [16]
    float* zpart  = a_s;              // gather scratch (a_s idle then): [4][256]
    __shared__ unsigned s_my;

    const int tid = threadIdx.x;
    const int bc  = blockIdx.x;
    const int grp = bc >> 4;
    const int j0  = bc * 4;
    // compute mapping: warp = k-split group (8 k per chunk)
    const int ks   = tid >> 5;        // 0..15
    const int lane = tid & 31;
    const int rg   = lane >> 1;       // 0..15 : rows rg + 16u, u<4
    const int cgp  = lane & 1;        // 0..1  : cols cgp*8 .. +7
    // staging mapping (128-k chunk: 64 rows x 128 k)
    const int kq4 = (tid & 31) * 4;   // 0..124
    const int r0  = tid >> 5;         // 0..15 : rows r0 + 16*rep
    // gate mapping
    const int gb  = (tid & 255) >> 2;
    const int gj  = tid & 3;

    for (int layer = 0; layer < 3; layer++) {
        const float* Wl = (layer == 0) ? W0 : ((layer == 1) ? W1 : W2);
        const float* Ul = (layer == 0) ? U0 : ((layer == 1) ? U1 : U2);
        const float* bl = (layer == 0) ? b0 : ((layer == 1) ? b1 : b2);
        const float* xsrc = (layer == 0) ? x0 : ((layer == 1) ? g_seqA : g_seqB);
        float* seqout = (layer == 0) ? g_seqA : ((layer == 1) ? g_seqB : (float*)0);
        const int K_in = (layer == 0) ? Dsz : Hsz;
        const int Ktot = K_in + Hsz;        // 768 or 1024
        const int nch  = Ktot >> 7;         // 6 or 8 chunks
        const int nx   = K_in >> 7;         // x-region chunks: 2 or 4

        // ---- weights resident in smem (once per layer) ----
        for (int idx = tid; idx < Ktot * 4; idx += NTHR) {
            int gk = idx >> 2, p = idx & 3;
            const float* wrow = (gk < K_in) ? (Wl + (size_t)gk * Gsz)
                                            : (Ul + (size_t)(gk - K_in) * Gsz);
            *(float4*)&w_s[gk * 16 + p * 4] = *(const float4*)(wrow + p * Hsz + j0);
        }
        if (tid < 16) bias_s[tid] = bl[(tid >> 2) * Hsz + j0 + (tid & 3)];
        float c_reg = 0.0f, hval = 0.0f;
        if (tid < 256) g_hbuf[0][gb * Hsz + j0 + gj] = 0.0f;
        int cur = 0;
        bar_arrive(&s_my, grp);   // publish zeroed h_0

        float4 st[4];
        #define LDG_CHUNK(TT, CI)                                                     \
            do {                                                                      \
                int kb_ = (CI) << 7;                                                  \
                if (kb_ < K_in) {                                                     \
                    const float* s_ = xsrc + (size_t)(TT) * K_in + kb_ + kq4;         \
                    _Pragma("unroll")                                                 \
                    for (int r_ = 0; r_ < 4; r_++)                                    \
                        st[r_] = *(const float4*)(s_ + (size_t)(r0 + 16 * r_) * Tsz * K_in); \
                } else {                                                              \
                    const float* s_ = hsrc + (kb_ - K_in) + kq4;                      \
                    _Pragma("unroll")                                                 \
                    for (int r_ = 0; r_ < 4; r_++)                                    \
                        st[r_] = *(const float4*)(s_ + (r0 + 16 * r_) * Hsz);         \
                }                                                                     \
            } while (0)

        #define STS_CHUNK(BUF)                                                        \
            do {                                                                      \
                float* ad_ = a_s + (BUF) * ABUF;                                      \
                _Pragma("unroll")                                                     \
                for (int r_ = 0; r_ < 4; r_++)                                        \
                    *(float4*)&ad_[(r0 + 16 * r_) * 132 + kq4] = st[r_];              \
            } while (0)

        // this warp's 8-k slice of chunk CI, from buffer BUF
        #define COMPUTE_CHUNK(BUF, CI)                                                \
            do {                                                                      \
                const float* wb = w_s + (((CI) << 7) + ks * 8) * 16;                  \
                const float* ab = a_s + (BUF) * ABUF + ks * 8;                        \
                _Pragma("unroll")                                                     \
                for (int kq = 0; kq < 2; kq++) {                                      \
                    float av[4][4];                                                   \
                    _Pragma("unroll")                                                 \
                    for (int u = 0; u < 4; u++)                                       \
                        *(float4*)av[u] = *(const float4*)&ab[(rg + 16 * u) * 132 + kq * 4]; \
                    _Pragma("unroll")                                                 \
                    for (int j = 0; j < 4; j++) {                                     \
                        const float* wr = wb + (kq * 4 + j) * 16 + cgp * 8;           \
                        ulonglong2 wlo = *(const ulonglong2*)wr;                      \
                        ulonglong2 whi = *(const ulonglong2*)(wr + 4);                \
                        _Pragma("unroll")                                             \
                        for (int u = 0; u < 4; u++) {                                 \
                            u64 ar = rep2(av[u][j]);                                  \
                            fma2(acc[u][0], ar, wlo.x);                               \
                            fma2(acc[u][1], ar, wlo.y);                               \
                            fma2(acc[u][2], ar, whi.x);                               \
                            fma2(acc[u][3], ar, whi.y);                               \
                        }                                                             \
                    }                                                                 \
                }                                                                     \
            } while (0)

        {
            const float* hsrc = g_hbuf[0];
            LDG_CHUNK(0, 0);   // step-0 chunk 0 (x region, barrier-independent)
            (void)hsrc;
        }

        for (int t = 0; t < Tsz; t++) {
            const float* hsrc = g_hbuf[cur];
            u64 acc[4][4] = {};
            int buf = 0;

            // ---- x phase (overlaps other blocks' arrival) ----
            STS_CHUNK(buf);
            if (nx > 1) LDG_CHUNK(t, 1);
            __syncthreads();
            for (int ci = 0; ci < nx; ci++) {
                if (ci + 1 < nx) {
                    STS_CHUNK(buf ^ 1);
                    if (ci + 2 < nx) LDG_CHUNK(t, ci + 2);
                }
                COMPUTE_CHUNK(buf, ci);
                if (ci + 1 < nx) { __syncthreads(); buf ^= 1; }
            }

            // ---- wait for h_t, then h phase ----
            bar_wait(&s_my);       // includes __syncthreads
            LDG_CHUNK(t, nx);
            STS_CHUNK(buf);
            if (nx + 1 < nch) LDG_CHUNK(t, nx + 1);
            __syncthreads();
            for (int ci = nx; ci < nch; ci++) {
                if (ci + 1 < nch) {
                    STS_CHUNK(buf ^ 1);
                    if (ci + 2 < nch) LDG_CHUNK(t, ci + 2);
                }
                COMPUTE_CHUNK(buf, ci);
                if (ci + 1 < nch) { __syncthreads(); buf ^= 1; }
            }

            // ---- k-split partials ----
            #pragma unroll
            for (int u = 0; u < 4; u++)
                #pragma unroll
                for (int p = 0; p < 4; p++)
                    *(float2*)&zred[ks * 1152 + (rg + 16 * u) * 18 + cgp * 8 + p * 2] =
                        *(float2*)&acc[u][p];
            __syncthreads();

            // ---- split gather: upper half sums groups 8..15 into zpart ----
            if (tid >= 256) {
                #pragma unroll
                for (int g = 0; g < 4; g++) {
                    int o = gb * 18 + g * 4 + gj;
                    float s = 0.0f;
                    #pragma unroll
                    for (int k = 8; k < 16; k++) s += zred[k * 1152 + o];
                    zpart[g * 256 + (tid - 256)] = s;
                }
            }
            __syncthreads();

            // ---- gates (tid < 256: one thread per (b, j)) ----
            if (tid < 256) {
                float z[4];
                #pragma unroll
                for (int g = 0; g < 4; g++) {
                    int o = gb * 18 + g * 4 + gj;
                    float s = bias_s[g * 4 + gj] + zpart[g * 256 + tid];
                    #pragma unroll
                    for (int k = 0; k < 8; k++) s += zred[k * 1152 + o];
                    z[g] = s;
                }
                float ig = fsig(z[0]);
                float fg = fsig(z[1]);
                float gg = ftanh(z[2]);
                float og = fsig(z[3]);
                c_reg = fg * c_reg + ig * gg;
                hval  = og * ftanh(c_reg);
                g_hbuf[cur ^ 1][gb * Hsz + j0 + gj] = hval;
                if (seqout) seqout[((size_t)(gb * Tsz + t)) * Hsz + j0 + gj] = hval;
            }
            cur ^= 1;

            bar_arrive(&s_my, grp);               // publish h_{t+1}
            if (t + 1 < Tsz) LDG_CHUNK(t + 1, 0); // prefetch next x chunk 0
        }
        bar_wait(&s_my);   // layer complete everywhere

        // ---- layer finals. Output: [out(=h2) | h0 | c0 | h1 | c1 | h2 | c2] ----
        if (tid < 256) {
            size_t off = (size_t)gb * Hsz + j0 + gj;
            const size_t S = (size_t)Bsz * Hsz;
            if (layer == 0)      { out[1 * S + off] = hval; out[2 * S + off] = c_reg; }
            else if (layer == 1) { out[3 * S + off] = hval; out[4 * S + off] = c_reg; }
            else                 { out[off] = hval; out[5 * S + off] = hval; out[6 * S + off] = c_reg; }
        }
        #undef LDG_CHUNK
        #undef STS_CHUNK
        #undef COMPUTE_CHUNK
    }
}

extern "C" void kernel_launch(void* const* d_in, const int* in_sizes, int n_in,
                              void* d_out, int out_size) {
    (void)in_sizes; (void)n_in; (void)out_size;
    static int attr_done = 0;
    if (!attr_done) {
        cudaFuncSetAttribute(lstm_kernel,
                             cudaFuncAttributeMaxDynamicSharedMemorySize, SMEM_BYTES);
        attr_done = 1;
    }
    lstm_kernel<<<NBLK, NTHR, SMEM_BYTES>>>(
        (const float*)d_in[0],
        (const float*)d_in[1], (const float*)d_in[2], (const float*)d_in[3],
        (const float*)d_in[4], (const float*)d_in[5], (const float*)d_in[6],
        (const float*)d_in[7], (const float*)d_in[8], (const float*)d_in[9],
        (float*)d_out);
}

// round 10
// speedup vs baseline: 1.0063x; 1.0063x over previous
#include <cuda_runtime.h>

// Stacked LSTM: B=64, T=512, D=256, H=512, 3 layers. fp32.
// Persistent kernel, 128 blocks x 1024 threads (32 warps), split-phase grid
// barrier per timestep. Block bc owns 4 hidden units => 16 z-columns.
// Per step: 64x16xK GEMM (K = D+H or 2H). Warp (ks, rh) computes a
// 32-row x 16-col x 16-k slice; per-thread 2x8 tile, packed f32x2 FFMA.
// Weights resident in smem per layer. A panel staged in 256-k superchunks.
// x-region superchunks computed between barrier arrive and wait.

#define Bsz 64
#define Tsz 512
#define Dsz 256
#define Hsz 512
#define Gsz 2048
#define NBLK 128
#define NTHR 1024

typedef unsigned long long u64;

// dynamic smem (floats):
//   w_s   [1024][16]   16384
//   a_s   [64][260]    16640   (one 256-k superchunk; row stride 260)
//   zred  [16][64][18] 18432
//   bias  [16]            16
#define SM_WS   0
#define SM_AS   16384
#define SM_ZRED (16384 + 16640)
#define SM_BIAS (16384 + 16640 + 18432)
#define SMEM_FLOATS (16384 + 16640 + 18432 + 16)
#define SMEM_BYTES (SMEM_FLOATS * 4)

__device__ float g_seqA[(size_t)Bsz * Tsz * Hsz];
__device__ float g_seqB[(size_t)Bsz * Tsz * Hsz];
__device__ float g_hbuf[2][Bsz * Hsz];
__device__ unsigned g_count = 0;
__device__ unsigned g_gen = 0;

// ---- split-phase grid barrier (snapshot-based; replay-safe) ----
__device__ __forceinline__ void bar_arrive(unsigned* s_my) {
    __syncthreads();
    if (threadIdx.x == 0) {
        unsigned my;
        asm volatile("ld.relaxed.gpu.u32 %0, [%1];" : "=r"(my) : "l"(&g_gen));
        *s_my = my;
        __threadfence();
        unsigned old = atomicAdd(&g_count, 1u);
        if (old == NBLK - 1) {
            g_count = 0;
            __threadfence();
            asm volatile("st.release.gpu.u32 [%0], %1;" :: "l"(&g_gen), "r"(my + 1u));
        }
    }
}
__device__ __forceinline__ void bar_wait(unsigned* s_my) {
    if (threadIdx.x == 0) {
        unsigned my = *s_my, g;
        do {
            asm volatile("ld.acquire.gpu.u32 %0, [%1];" : "=r"(g) : "l"(&g_gen));
        } while (g == my);
    }
    __syncthreads();
}

__device__ __forceinline__ float fsig(float x) {
    return __fdividef(1.0f, 1.0f + __expf(-x));
}
__device__ __forceinline__ float ftanh(float x) {
    float e = __expf(2.0f * x);
    return 1.0f - __fdividef(2.0f, e + 1.0f);
}
__device__ __forceinline__ void fma2(u64& d, u64 a, u64 b) {
    asm("fma.rn.f32x2 %0, %1, %2, %0;" : "+l"(d) : "l"(a), "l"(b));
}
__device__ __forceinline__ u64 rep2(float x) {
    u64 r;
    asm("mov.b64 %0, {%1, %1};" : "=l"(r) : "f"(x));
    return r;
}

extern "C" __global__ void __launch_bounds__(NTHR, 1)
lstm_kernel(const float* __restrict__ x0,
            const float* __restrict__ W0, const float* __restrict__ U0, const float* __restrict__ b0,
            const float* __restrict__ W1, const float* __restrict__ U1, const float* __restrict__ b1,
            const float* __restrict__ W2, const float* __restrict__ U2, const float* __restrict__ b2,
            float* __restrict__ out)
{
    extern __shared__ float smem[];
    float* w_s    = smem + SM_WS;     // [k][16]
    float* a_s    = smem + SM_AS;     // [64][260]
    float* zred   = smem + SM_ZRED;   // [16][64][18]
    float* bias_s = smem + SM_BIAS;   // [16]
    float* zpart  = a_s;              // gather scratch: [4][256] (a_s idle then)
    __shared__ unsigned s_my;

    const int tid = threadIdx.x;
    const int bc  = blockIdx.x;
    const int j0  = bc * 4;
    // compute mapping: warp = (k-group, row-half)
    const int wid  = tid >> 5;        // 0..31
    const int ks   = wid >> 1;        // 0..15 k-group (16 k per superchunk)
    const int rh   = wid & 1;         // 0..1  row half (32 rows)
    const int lane = tid & 31;
    const int rg   = lane >> 1;       // 0..15 : rows rh*32 + rg + 16u, u<2
    const int cgp  = lane & 1;        // 0..1  : cols cgp*8 .. +7
    // staging mapping (256-k superchunk: 64 rows x 256 k, 1024 threads)
    const int kq4 = (tid & 63) * 4;   // 0..252
    const int r0  = tid >> 6;         // 0..15 : rows r0 + 16*rep, rep<4
    // gate mapping (tid < 256)
    const int gb  = (tid & 255) >> 2;
    const int gj  = tid & 3;

    for (int layer = 0; layer < 3; layer++) {
        const float* Wl = (layer == 0) ? W0 : ((layer == 1) ? W1 : W2);
        const float* Ul = (layer == 0) ? U0 : ((layer == 1) ? U1 : U2);
        const float* bl = (layer == 0) ? b0 : ((layer == 1) ? b1 : b2);
        const float* xsrc = (layer == 0) ? x0 : ((layer == 1) ? g_seqA : g_seqB);
        float* seqout = (layer == 0) ? g_seqA : ((layer == 1) ? g_seqB : (float*)0);
        const int K_in = (layer == 0) ? Dsz : Hsz;
        const int Ktot = K_in + Hsz;        // 768 or 1024
        const int nsc  = Ktot >> 8;         // superchunks: 3 or 4
        const int nx   = K_in >> 8;         // x-region superchunks: 1 or 2

        // ---- weights resident in smem (once per layer) ----
        for (int idx = tid; idx < Ktot * 4; idx += NTHR) {
            int gk = idx >> 2, p = idx & 3;
            const float* wrow = (gk < K_in) ? (Wl + (size_t)gk * Gsz)
                                            : (Ul + (size_t)(gk - K_in) * Gsz);
            *(float4*)&w_s[gk * 16 + p * 4] = *(const float4*)(wrow + p * Hsz + j0);
        }
        if (tid < 16) bias_s[tid] = bl[(tid >> 2) * Hsz + j0 + (tid & 3)];
        float c_reg = 0.0f, hval = 0.0f;
        if (tid < 256) g_hbuf[0][gb * Hsz + j0 + gj] = 0.0f;
        int cur = 0;
        bar_arrive(&s_my);   // publish zeroed h_0

        float4 st[4];
        // stage superchunk SC of step TT into registers (coalesced rows)
        #define LDG_SC(TT, SC)                                                        \
            do {                                                                      \
                if ((SC) < nx) {                                                      \
                    const float* s_ = xsrc + (size_t)(TT) * K_in + (SC) * 256 + kq4;  \
                    _Pragma("unroll")                                                 \
                    for (int r_ = 0; r_ < 4; r_++)                                    \
                        st[r_] = *(const float4*)(s_ + (size_t)(r0 + 16 * r_) * Tsz * K_in); \
                } else {                                                              \
                    const float* s_ = hsrc + ((SC) * 256 - K_in) + kq4;               \
                    _Pragma("unroll")                                                 \
                    for (int r_ = 0; r_ < 4; r_++)                                    \
                        st[r_] = *(const float4*)(s_ + (r0 + 16 * r_) * Hsz);         \
                }                                                                     \
            } while (0)

        #define STS_SC()                                                              \
            do {                                                                      \
                _Pragma("unroll")                                                     \
                for (int r_ = 0; r_ < 4; r_++)                                        \
                    *(float4*)&a_s[(r0 + 16 * r_) * 260 + kq4] = st[r_];              \
            } while (0)

        // this warp's 16-k, 32-row slice of superchunk SC
        #define COMPUTE_SC(SC)                                                        \
            do {                                                                      \
                const float* wb = w_s + ((SC) * 256 + ks * 16) * 16;                  \
                const float* ab = a_s + ks * 16;                                      \
                _Pragma("unroll")                                                     \
                for (int kq = 0; kq < 4; kq++) {                                      \
                    float av[2][4];                                                   \
                    _Pragma("unroll")                                                 \
                    for (int u = 0; u < 2; u++)                                       \
                        *(float4*)av[u] = *(const float4*)&ab[(rh * 32 + rg + 16 * u) * 260 + kq * 4]; \
                    _Pragma("unroll")                                                 \
                    for (int j = 0; j < 4; j++) {                                     \
                        const float* wr = wb + (kq * 4 + j) * 16 + cgp * 8;           \
                        ulonglong2 wlo = *(const ulonglong2*)wr;                      \
                        ulonglong2 whi = *(const ulonglong2*)(wr + 4);                \
                        _Pragma("unroll")                                             \
                        for (int u = 0; u < 2; u++) {                                 \
                            u64 ar = rep2(av[u][j]);                                  \
                            fma2(acc[u][0], ar, wlo.x);                               \
                            fma2(acc[u][1], ar, wlo.y);                               \
                            fma2(acc[u][2], ar, whi.x);                               \
                            fma2(acc[u][3], ar, whi.y);                               \
                        }                                                             \
                    }                                                                 \
                }                                                                     \
            } while (0)

        {
            const float* hsrc = g_hbuf[0];
            LDG_SC(0, 0);   // step-0 x superchunk (barrier-independent)
            (void)hsrc;
        }

        for (int t = 0; t < Tsz; t++) {
            const float* hsrc = g_hbuf[cur];
            u64 acc[2][4] = {};

            // ---- x phase (overlaps other blocks' barrier arrival) ----
            for (int sc = 0; sc < nx; sc++) {
                STS_SC();
                if (sc + 1 < nx) LDG_SC(t, sc + 1);
                __syncthreads();
                COMPUTE_SC(sc);
                __syncthreads();
            }

            // ---- wait for h_t, then h phase ----
            bar_wait(&s_my);
            LDG_SC(t, nx);
            for (int sc = nx; sc < nsc; sc++) {
                STS_SC();
                if (sc + 1 < nsc) LDG_SC(t, sc + 1);
                __syncthreads();
                COMPUTE_SC(sc);
                __syncthreads();
            }

            // ---- k-split partials ----
            #pragma unroll
            for (int u = 0; u < 2; u++)
                #pragma unroll
                for (int p = 0; p < 4; p++)
                    *(float2*)&zred[ks * 1152 + (rh * 32 + rg + 16 * u) * 18 + cgp * 8 + p * 2] =
                        *(float2*)&acc[u][p];
            __syncthreads();

            // ---- split gather: threads 256..511 sum groups 8..15 into zpart ----
            if ((tid >> 8) == 1) {
                #pragma unroll
                for (int g = 0; g < 4; g++) {
                    int o = gb * 18 + g * 4 + gj;
                    float s = 0.0f;
                    #pragma unroll
                    for (int k = 8; k < 16; k++) s += zred[k * 1152 + o];
                    zpart[g * 256 + (tid & 255)] = s;
                }
            }
            __syncthreads();

            // ---- gates (tid < 256: one thread per (b, j)) ----
            if (tid < 256) {
                float z[4];
                #pragma unroll
                for (int g = 0; g < 4; g++) {
                    int o = gb * 18 + g * 4 + gj;
                    float s = bias_s[g * 4 + gj] + zpart[g * 256 + tid];
                    #pragma unroll
                    for (int k = 0; k < 8; k++) s += zred[k * 1152 + o];
                    z[g] = s;
                }
                float ig = fsig(z[0]);
                float fg = fsig(z[1]);
                float gg = ftanh(z[2]);
                float og = fsig(z[3]);
                c_reg = fg * c_reg + ig * gg;
                hval  = og * ftanh(c_reg);
                g_hbuf[cur ^ 1][gb * Hsz + j0 + gj] = hval;
                if (seqout) seqout[((size_t)(gb * Tsz + t)) * Hsz + j0 + gj] = hval;
            }
            cur ^= 1;

            bar_arrive(&s_my);                  // publish h_{t+1}
            if (t + 1 < Tsz) LDG_SC(t + 1, 0);  // prefetch next x superchunk
        }
        bar_wait(&s_my);   // layer complete everywhere

        // ---- layer finals. Output: [out(=h2) | h0 | c0 | h1 | c1 | h2 | c2] ----
        if (tid < 256) {
            size_t off = (size_t)gb * Hsz + j0 + gj;
            const size_t S = (size_t)Bsz * Hsz;
            if (layer == 0)      { out[1 * S + off] = hval; out[2 * S + off] = c_reg; }
            else if (layer == 1) { out[3 * S + off] = hval; out[4 * S + off] = c_reg; }
            else                 { out[off] = hval; out[5 * S + off] = hval; out[6 * S + off] = c_reg; }
        }
        #undef LDG_SC
        #undef STS_SC
        #undef COMPUTE_SC
    }
}

extern "C" void kernel_launch(void* const* d_in, const int* in_sizes, int n_in,
                              void* d_out, int out_size) {
    (void)in_sizes; (void)n_in; (void)out_size;
    static int attr_done = 0;
    if (!attr_done) {
        cudaFuncSetAttribute(lstm_kernel,
                             cudaFuncAttributeMaxDynamicSharedMemorySize, SMEM_BYTES);
        attr_done = 1;
    }
    lstm_kernel<<<NBLK, NTHR, SMEM_BYTES>>>(
        (const float*)d_in[0],
        (const float*)d_in[1], (const float*)d_in[2], (const float*)d_in[3],
        (const float*)d_in[4], (const float*)d_in[5], (const float*)d_in[6],
        (const float*)d_in[7], (const float*)d_in[8], (const float*)d_in[9],
        (float*)d_out);
}